// round 8
// baseline (speedup 1.0000x reference)
#include <cuda_runtime.h>
#include <cstdint>

#define BB 8
#define TT 128
#define DD 512
#define OO 512
#define CPG 8              // CTAs per cluster (one cluster per batch)
#define OSL (OO/CPG)       // 64  output-col slice per CTA
#define NTH 256
#define FULLMASK 0xffffffffu

// ---------------- device scratch (no allocations allowed) ----------------
__device__ float g_UaH[BB*TT*OO];   // inputs@Ua + Ba
__device__ float g_IC [BB*TT*OO];   // inputs@Co
__device__ float g_XUo[BB*TT*OO];   // inputs@Uo
__device__ float g_embWo[OO];       // emb@Wo

// ---------------- helpers ----------------
__device__ __forceinline__ float wredsum(float v) {
    #pragma unroll
    for (int s = 16; s; s >>= 1) v += __shfl_xor_sync(FULLMASK, v, s);
    return v;
}
__device__ __forceinline__ float tanhapx(float x) {
    float y;
    asm("tanh.approx.f32 %0, %1;" : "=f"(y) : "f"(x));
    return y;
}
__device__ __forceinline__ uint32_t smem_u32(const void* p) {
    uint32_t a;
    asm("{ .reg .u64 t; cvta.to.shared.u64 t, %1; cvt.u32.u64 %0, t; }"
        : "=r"(a) : "l"(p));
    return a;
}
__device__ __forceinline__ uint32_t dsm_map(uint32_t laddr, uint32_t rank) {
    uint32_t r;
    asm("mapa.shared::cluster.u32 %0, %1, %2;" : "=r"(r) : "r"(laddr), "r"(rank));
    return r;
}
__device__ __forceinline__ void mbar_init(uint32_t a, uint32_t cnt) {
    asm volatile("mbarrier.init.shared.b64 [%0], %1;" :: "r"(a), "r"(cnt) : "memory");
}
__device__ __forceinline__ void mbar_arm(uint32_t a, uint32_t tx) {
    asm volatile("mbarrier.arrive.expect_tx.shared.b64 _, [%0], %1;"
                 :: "r"(a), "r"(tx) : "memory");
}
__device__ __forceinline__ void mbar_wait(uint32_t a, uint32_t parity) {
    asm volatile(
        "{\n\t.reg .pred P;\n\t"
        "W_%=:\n\t"
        "mbarrier.try_wait.parity.acquire.cluster.shared::cta.b64 P, [%0], %1, 0x989680;\n\t"
        "@!P bra W_%=;\n\t}"
        :: "r"(a), "r"(parity) : "memory");
}
// fire-and-forget remote store, completion counted on remote mbarrier (bytes)
__device__ __forceinline__ void st_async(uint32_t raddr, float v, uint32_t rbar) {
    asm volatile(
        "st.async.shared::cluster.mbarrier::complete_tx::bytes.b32 [%0], %1, [%2];"
        :: "r"(raddr), "r"(__float_as_uint(v)), "r"(rbar) : "memory");
}
#define CLUSTER_SYNC() do { \
    asm volatile("barrier.cluster.arrive.aligned;" ::: "memory"); \
    asm volatile("barrier.cluster.wait.aligned;"   ::: "memory"); \
} while (0)

// packed fp32x2 fma: d += a*b (two fp32 lanes per instruction)
__device__ __forceinline__ void fma2(unsigned long long& d,
                                     unsigned long long a, unsigned long long b) {
    asm("fma.rn.f32x2 %0, %1, %2, %0;" : "+l"(d) : "l"(a), "l"(b));
}
__device__ __forceinline__ unsigned long long pack2(float x, float y) {
    unsigned long long r;
    asm("mov.b64 %0, {%1, %2};" : "=l"(r) : "f"(x), "f"(y));
    return r;
}
__device__ __forceinline__ float2 unpack2(unsigned long long v) {
    float2 r;
    asm("mov.b64 {%0, %1}, %2;" : "=f"(r.x), "=f"(r.y) : "l"(v));
    return r;
}

// =======================================================================
// GEMM (fp32x2, conflict-free): C_z = A[1024x512] @ B_z[512x512]
// 64x64 tile, BK=32, double-buffered smem, 256 threads, 4x4/thread.
//   A tile: plain k-major float[32][64]; m-pairs read as ulonglong2
//           (2 distinct addrs/warp -> broadcast, conflict-free).
//   B tile: dup pairs (b,b) at permuted pos(n)=(n&3)*16+(n>>2), XOR-swizzled
//           by kk -> both the 4x LDS.64 reads and the STS.64 are conflict-free.
// =======================================================================
#define SWZB(kk, pos) ((pos) ^ (((kk) & 3) << 2))

__global__ __launch_bounds__(256) void gemm3_kernel(
    const float* __restrict__ A,
    const float* __restrict__ Ua,
    const float* __restrict__ Co,
    const float* __restrict__ Uo,
    const float* __restrict__ Ba)
{
    __shared__ float As[2][32][64];                  // 16 KB
    __shared__ unsigned long long Bs2[2][32][64];    // 32 KB  (total 48 KB)

    const int m0 = blockIdx.x * 64;
    const int n0 = blockIdx.y * 64;
    const int z  = blockIdx.z;
    const float* __restrict__ Bm = (z == 0) ? Ua : ((z == 1) ? Co : Uo);
    float* Cout = (z == 0) ? g_UaH : ((z == 1) ? g_IC : g_XUo);

    const int tid  = threadIdx.x;
    const int tx   = tid & 15;
    const int ty   = tid >> 4;
    const int la_m = tid >> 2;            // 0..63
    const int la_k = (tid & 3) << 3;      // 0,8,16,24
    const int lb_k = tid >> 3;            // 0..31
    const int lb_n = (tid & 7) << 3;      // 0..56

    unsigned long long acc2[2][4];
    #pragma unroll
    for (int i = 0; i < 2; i++)
        #pragma unroll
        for (int j = 0; j < 4; j++) acc2[i][j] = 0ull;

    float4 a0v = *(const float4*)&A[(m0 + la_m) * DD + la_k];
    float4 a1v = *(const float4*)&A[(m0 + la_m) * DD + la_k + 4];
    float4 b0v = *(const float4*)&Bm[lb_k * OO + n0 + lb_n];
    float4 b1v = *(const float4*)&Bm[lb_k * OO + n0 + lb_n + 4];

    // stage 0
    {
        As[0][la_k+0][la_m]=a0v.x; As[0][la_k+1][la_m]=a0v.y;
        As[0][la_k+2][la_m]=a0v.z; As[0][la_k+3][la_m]=a0v.w;
        As[0][la_k+4][la_m]=a1v.x; As[0][la_k+5][la_m]=a1v.y;
        As[0][la_k+6][la_m]=a1v.z; As[0][la_k+7][la_m]=a1v.w;
        float bb[8] = {b0v.x,b0v.y,b0v.z,b0v.w,b1v.x,b1v.y,b1v.z,b1v.w};
        #pragma unroll
        for (int c = 0; c < 8; c++) {
            int n = lb_n + c;
            int pos = ((n & 3) << 4) + (n >> 2);
            Bs2[0][lb_k][SWZB(lb_k, pos)] = pack2(bb[c], bb[c]);
        }
    }
    __syncthreads();

    int cur = 0;
    for (int k0 = 0; k0 < DD; k0 += 32) {
        if (k0 + 32 < DD) {
            a0v = *(const float4*)&A[(m0 + la_m) * DD + k0 + 32 + la_k];
            a1v = *(const float4*)&A[(m0 + la_m) * DD + k0 + 32 + la_k + 4];
            b0v = *(const float4*)&Bm[(k0 + 32 + lb_k) * OO + n0 + lb_n];
            b1v = *(const float4*)&Bm[(k0 + 32 + lb_k) * OO + n0 + lb_n + 4];
        }
        #pragma unroll
        for (int kk = 0; kk < 32; kk++) {
            ulonglong2 av = *(const ulonglong2*)&As[cur][kk][ty << 2];
            unsigned long long b0 = Bs2[cur][kk][SWZB(kk,  0 + tx)];
            unsigned long long b1 = Bs2[cur][kk][SWZB(kk, 16 + tx)];
            unsigned long long b2 = Bs2[cur][kk][SWZB(kk, 32 + tx)];
            unsigned long long b3 = Bs2[cur][kk][SWZB(kk, 48 + tx)];
            fma2(acc2[0][0], av.x, b0); fma2(acc2[1][0], av.y, b0);
            fma2(acc2[0][1], av.x, b1); fma2(acc2[1][1], av.y, b1);
            fma2(acc2[0][2], av.x, b2); fma2(acc2[1][2], av.y, b2);
            fma2(acc2[0][3], av.x, b3); fma2(acc2[1][3], av.y, b3);
        }
        if (k0 + 32 < DD) {
            const int nxt = cur ^ 1;
            As[nxt][la_k+0][la_m]=a0v.x; As[nxt][la_k+1][la_m]=a0v.y;
            As[nxt][la_k+2][la_m]=a0v.z; As[nxt][la_k+3][la_m]=a0v.w;
            As[nxt][la_k+4][la_m]=a1v.x; As[nxt][la_k+5][la_m]=a1v.y;
            As[nxt][la_k+6][la_m]=a1v.z; As[nxt][la_k+7][la_m]=a1v.w;
            float bb[8] = {b0v.x,b0v.y,b0v.z,b0v.w,b1v.x,b1v.y,b1v.z,b1v.w};
            #pragma unroll
            for (int c = 0; c < 8; c++) {
                int n = lb_n + c;
                int pos = ((n & 3) << 4) + (n >> 2);
                Bs2[nxt][lb_k][SWZB(lb_k, pos)] = pack2(bb[c], bb[c]);
            }
            __syncthreads();
            cur = nxt;
        }
    }

    #pragma unroll
    for (int mp = 0; mp < 2; mp++) {
        #pragma unroll
        for (int j = 0; j < 4; j++) {
            float2 v = unpack2(acc2[mp][j]);
            int r = m0 + (ty << 2) + (mp << 1);
            int c = n0 + (tx << 2) + j;
            float add = (z == 0) ? Ba[c] : 0.f;
            Cout[(size_t)r       * OO + c] = v.x + add;
            Cout[(size_t)(r + 1) * OO + c] = v.y + add;
        }
    }
}

// =======================================================================
// embWo[i] = sum_j emb[i][j] * Wo[j]
// =======================================================================
__global__ __launch_bounds__(256) void embwo_kernel(
    const float* __restrict__ emb, const float* __restrict__ Wo)
{
    const int row  = (blockIdx.x << 3) + (threadIdx.x >> 5);
    const int lane = threadIdx.x & 31;
    const float* rp = emb + row * OO;
    float acc = 0.f;
    #pragma unroll 4
    for (int j = lane; j < OO; j += 32) acc += rp[j] * Wo[j];
    acc = wredsum(acc);
    if (lane == 0) g_embWo[row] = acc;
}

// =======================================================================
// Persistent clustered scan: st.async + tx-mbarriers (R7 protocol),
// WaS reduced by quad-shuffle (one less block barrier), woy in tail.
// =======================================================================
#define UAH_PITCH 68
#define SG_PITCH  68        // 64 sig + 4 scalar slots per rank (272B = 17x16 aligned)
// shared memory layout (float offsets)
#define UAH_OFF   0                              // [128][68] = 8704
#define IC_OFF    (UAH_OFF + TT*UAH_PITCH)       // [128][64] = 8192
#define SG_OFF    (IC_OFF + TT*OSL)              // 2 x [8][68] = 1088
#define SPART_OFF (SG_OFF + 2*CPG*SG_PITCH)      // 2 x [8][128] = 2048
#define WAS_OFF   (SPART_OFF + 2*CPG*TT)         // [64]
#define WBUF_OFF  (WAS_OFF + OSL)                // [128]
#define RED_OFF   (WBUF_OFF + TT)                // [32]
#define PART_OFF  (RED_OFF + 32)                 // [256] (P2 scores / P3 ctx)
#define BAR_OFF   (PART_OFF + 256)               // 4 x u64 (score0,score1,sig0,sig1)
#define SMEM_FLOATS (BAR_OFF + 8)
#define SMEM_BYTES  (SMEM_FLOATS * 4)

#define TX_SCORE (CPG*TT*4)          // 4096 bytes/phase
#define TX_SIG   (CPG*(OSL+4)*4)     // 2176 bytes/phase

__global__ __launch_bounds__(NTH, 1) __cluster_dims__(CPG, 1, 1)
void scan_kernel(const float* __restrict__ Wa,
                 const float* __restrict__ Va,
                 const float* __restrict__ Bo,
                 float* __restrict__ out)
{
    extern __shared__ float sm[];
    float* UaH_s = sm + UAH_OFF;
    float* IC_s  = sm + IC_OFF;
    float* wbuf  = sm + WBUF_OFF;
    float* WaS_s = sm + WAS_OFF;
    float* red   = sm + RED_OFF;
    float* partB = sm + PART_OFF;

    const uint32_t sbase   = smem_u32(sm);
    const uint32_t barbase = sbase + BAR_OFF * 4;

    const int tid  = threadIdx.x;
    const int lane = tid & 31;
    const int wid  = tid >> 5;
    const int b    = blockIdx.x >> 3;     // batch
    const int crk  = blockIdx.x & 7;      // cluster rank
    const int o_base = crk * OSL;
    const int oc   = tid & 63;            // P3 ctx split
    const int kc   = tid >> 6;            // P3 ctx split (0..3)
    const int ts   = tid & 127;           // P2 timestep
    const int q    = tid >> 7;            // P2 o-half
    const int col4 = tid >> 2;            // WaS col (0..63)
    const int kq   = tid & 3;             // WaS k-quarter

    // ---------------- prologue ----------------
    for (int i = tid; i < TT * OSL; i += NTH) {
        int tt = i >> 6, o = i & 63;
        UaH_s[tt * UAH_PITCH + o] = g_UaH[(size_t)(b * TT + tt) * OO + o_base + o];
        IC_s[(tt << 6) + o]       = g_IC [(size_t)(b * TT + tt) * OO + o_base + o];
    }

    // Wa slice packed: thread (col4,kq) holds k in [kq*128, kq*128+128)
    unsigned long long wreg2[64];
    {
        const int colg = o_base + col4;
        #pragma unroll
        for (int m = 0; m < 64; m++) {
            float w0 = Wa[(size_t)(kq * 128 + 2 * m)     * OO + colg];
            float w1 = Wa[(size_t)(kq * 128 + 2 * m + 1) * OO + colg];
            wreg2[m] = pack2(w0, w1);
        }
    }
    float va_r[32];
    #pragma unroll
    for (int j = 0; j < 32; j++) va_r[j] = Va[o_base + (q << 5) + j];

    const float ew0   = g_embWo[tid];
    const float ew1   = g_embWo[tid + 256];
    const float ew_sl = g_embWo[o_base + oc];
    const float bo_r  = (tid < OSL) ? Bo[o_base + tid] : 0.f;

    uint32_t rbase[CPG];
    #pragma unroll
    for (int r = 0; r < CPG; r++) rbase[r] = dsm_map(sbase, r);

    if (tid == 0) {
        #pragma unroll
        for (int i = 0; i < 4; i++) mbar_init(barbase + i * 8, 1);
        mbar_arm(barbase + 0,  TX_SCORE);
        mbar_arm(barbase + 8,  TX_SCORE);
        mbar_arm(barbase + 16, TX_SIG);
        mbar_arm(barbase + 24, TX_SIG);
    }

    // t=0 seed: sig(-1)=0.5, S=512, P=sum(embWo) in sg buffer 1
    float p0p = wredsum(ew0 + ew1);
    if (lane == 0) red[wid] = p0p;
    {
        float* sg1 = sm + SG_OFF + CPG * SG_PITCH;
        for (int i = tid; i < CPG * SG_PITCH; i += NTH)
            sg1[i] = ((i % SG_PITCH) < OSL) ? 0.5f : 0.f;
    }
    __syncthreads();
    if (tid == 0) {
        float P0 = 0.f;
        #pragma unroll
        for (int i = 0; i < 8; i++) P0 += red[i];
        float* sg1 = sm + SG_OFF + CPG * SG_PITCH;
        sg1[OSL + 0] = 512.f;
        sg1[OSL + 2] = P0;
    }
    __syncthreads();
    CLUSTER_SYNC();   // barriers initialized+armed everywhere before any st.async

    // ---------------- scan over T steps ----------------
    for (int t = 0; t < TT; t++) {
        const int buf = t & 1;

        float xo = 0.f;
        if (tid < OSL)
            xo = __ldg(&g_XUo[(size_t)(b * TT + ((t + TT - 1) & (TT - 1))) * OO + o_base + tid]);

        // -------- wait for sig/scalars of pred(t-1) --------
        const uint32_t sigbar_l = barbase + 16 + (buf ^ 1) * 8;
        if (t > 0) {
            mbar_wait(sigbar_l, ((t - 1) >> 1) & 1);
            if (tid == 0) mbar_arm(sigbar_l, TX_SIG);
        }
        const float* sgc = sm + SG_OFF + (buf ^ 1) * (CPG * SG_PITCH);

        // -------- WaS (fp32x2, quad-shuffle reduce) --------
        {
            unsigned long long acc2 = 0ull;
            #pragma unroll
            for (int rr = 0; rr < 2; rr++) {
                const ulonglong2* sp2 =
                    (const ulonglong2*)(sgc + (2 * kq + rr) * SG_PITCH);
                #pragma unroll
                for (int i = 0; i < 16; i++) {
                    ulonglong2 sv = sp2[i];
                    fma2(acc2, sv.x, wreg2[rr * 32 + 2 * i]);
                    fma2(acc2, sv.y, wreg2[rr * 32 + 2 * i + 1]);
                }
            }
            float2 f = unpack2(acc2);
            float w = f.x + f.y;
            w += __shfl_xor_sync(FULLMASK, w, 1);
            w += __shfl_xor_sync(FULLMASK, w, 2);
            if (kq == 0) WaS_s[col4] = w;
        }
        __syncthreads();                                   // s1: WaS_s ready

        // -------- P2: partial scores, all t, own o-half --------
        {
            const float* urow = UaH_s + ts * UAH_PITCH + (q << 5);
            const float* wp   = WaS_s + (q << 5);
            float acc = 0.f;
            #pragma unroll
            for (int j = 0; j < 8; j++) {
                float4 u = *(const float4*)&urow[j << 2];
                float4 w = *(const float4*)&wp[j << 2];
                acc += tanhapx(u.x + w.x) * va_r[(j << 2) + 0]
                     + tanhapx(u.y + w.y) * va_r[(j << 2) + 1]
                     + tanhapx(u.z + w.z) * va_r[(j << 2) + 2]
                     + tanhapx(u.w + w.w) * va_r[(j << 2) + 3];
            }
            partB[(q << 7) + ts] = acc;
        }
        __syncthreads();                                   // s2
        if (tid < TT) {
            float s = partB[tid] + partB[128 + tid];
            const uint32_t doff = (uint32_t)(SPART_OFF + buf * (CPG * TT) + crk * TT + tid) * 4u;
            const uint32_t boff = (uint32_t)(BAR_OFF * 4 + buf * 8);
            #pragma unroll
            for (int r = 0; r < CPG; r++)
                st_async(rbase[r] + doff, s, rbase[r] + boff);
        }

        // -------- wait for all score partials --------
        const uint32_t scorebar_l = barbase + buf * 8;
        mbar_wait(scorebar_l, (t >> 1) & 1);
        if (tid == 0) mbar_arm(scorebar_l, TX_SCORE);

        // -------- P3: softmax over T + ctx + pred + sig broadcast --------
        const float* sp = sm + SPART_OFF + buf * (CPG * TT);
        if (tid < TT) {
            float sc = 0.f;
            #pragma unroll
            for (int r = 0; r < CPG; r++) sc += sp[(r << 7) + tid];
            float esv = __expf(sc);                        // |score| small: no max-sub
            wbuf[tid] = esv;
            float spp = wredsum(esv);
            if (lane == 0) red[wid] = spp;                 // wid 0..3
        }
        __syncthreads();                                   // s3: wbuf + red
        const float esum = (red[0] + red[1]) + (red[2] + red[3]);

        // ctx partial: thread (oc,kc) covers t' in [kc*32, kc*32+32)
        {
            float acc = 0.f;
            const int base = kc << 5;
            #pragma unroll
            for (int j = 0; j < 8; j++) {
                float4 wb = *(const float4*)&wbuf[base + (j << 2)];
                acc += wb.x * IC_s[((base + (j << 2) + 0) << 6) + oc]
                     + wb.y * IC_s[((base + (j << 2) + 1) << 6) + oc]
                     + wb.z * IC_s[((base + (j << 2) + 2) << 6) + oc]
                     + wb.w * IC_s[((base + (j << 2) + 3) << 6) + oc];
            }
            partB[tid] = acc;
        }
        __syncthreads();                                   // s4
        if (tid < OSL) {
            float S = 0.f, P = 0.f;
            #pragma unroll
            for (int r = 0; r < CPG; r++) {
                const float* sr = sgc + r * SG_PITCH + OSL;
                S += sr[0] + sr[1];
                P += sr[2] + sr[3];
            }
            const float woy = __fdividef(P, S);
            float ctx  = partB[tid] + partB[64 + tid] + partB[128 + tid] + partB[192 + tid];
            float pred = woy + xo + __fdividef(ctx, esum) + bo_r;
            out[(size_t)(b * TT + t) * OO + o_base + tid] = pred;

            // sigmoid + exp partials of pred(t), broadcast to all ranks
            float e  = __expf(pred);
            float sg = __fdividef(1.f, 1.f + __expf(-pred));
            float pe = wredsum(e);            // warp-local (tids 0-31 / 32-63)
            float pp = wredsum(e * ew_sl);
            if (t < TT - 1) {
                const uint32_t sgoff =
                    (uint32_t)(SG_OFF + buf * (CPG * SG_PITCH) + crk * SG_PITCH + tid) * 4u;
                const uint32_t sboff = (uint32_t)(BAR_OFF * 4 + 16 + buf * 8);
                #pragma unroll
                for (int r = 0; r < CPG; r++)
                    st_async(rbase[r] + sgoff, sg, rbase[r] + sboff);
                if (lane == 0) {
                    const int w = tid >> 5;    // 0 or 1
                    const uint32_t so =
                        (uint32_t)(SG_OFF + buf * (CPG * SG_PITCH) + crk * SG_PITCH + OSL + w) * 4u;
                    const uint32_t po = so + 8u;
                    #pragma unroll
                    for (int r = 0; r < CPG; r++) {
                        st_async(rbase[r] + so, pe, rbase[r] + sboff);
                        st_async(rbase[r] + po, pp, rbase[r] + sboff);
                    }
                }
            }
        }
    }
    CLUSTER_SYNC();   // no CTA exits while peers' in-flight stores may target it
}

// =======================================================================
// launch
// =======================================================================
extern "C" void kernel_launch(void* const* d_in, const int* in_sizes, int n_in,
                              void* d_out, int out_size)
{
    const float* inputs = (const float*)d_in[0];
    const float* Wa     = (const float*)d_in[1];
    const float* Ua     = (const float*)d_in[2];
    const float* Va     = (const float*)d_in[3];
    const float* Ba     = (const float*)d_in[4];
    const float* Wo     = (const float*)d_in[5];
    const float* Uo     = (const float*)d_in[6];
    const float* Co     = (const float*)d_in[7];
    const float* Bo     = (const float*)d_in[8];
    const float* emb    = (const float*)d_in[9];
    float* out = (float*)d_out;

    dim3 g(16, 8, 3);
    gemm3_kernel<<<g, 256>>>(inputs, Ua, Co, Uo, Ba);
    embwo_kernel<<<64, 256>>>(emb, Wo);

    cudaFuncSetAttribute(scan_kernel,
                         cudaFuncAttributeMaxDynamicSharedMemorySize, SMEM_BYTES);
    scan_kernel<<<BB * CPG, NTH, SMEM_BYTES>>>(Wa, Va, Bo, out);
}

// round 9
// speedup vs baseline: 1.1905x; 1.1905x over previous
#include <cuda_runtime.h>
#include <cstdint>

#define BB 8
#define TT 128
#define DD 512
#define OO 512
#define CPG 8              // CTAs per cluster (one cluster per batch)
#define OSL (OO/CPG)       // 64  output-col slice per CTA
#define NTH 256
#define FULLMASK 0xffffffffu

// ---------------- device scratch (no allocations allowed) ----------------
__device__ float g_UaH[BB*TT*OO];   // inputs@Ua + Ba
__device__ float g_IC [BB*TT*OO];   // inputs@Co
__device__ float g_XUo[BB*TT*OO];   // inputs@Uo
__device__ float g_embWo[OO];       // emb@Wo

// ---------------- helpers ----------------
__device__ __forceinline__ float wredsum(float v) {
    #pragma unroll
    for (int s = 16; s; s >>= 1) v += __shfl_xor_sync(FULLMASK, v, s);
    return v;
}
__device__ __forceinline__ float tanhapx(float x) {
    float y;
    asm("tanh.approx.f32 %0, %1;" : "=f"(y) : "f"(x));
    return y;
}
__device__ __forceinline__ uint32_t smem_u32(const void* p) {
    uint32_t a;
    asm("{ .reg .u64 t; cvta.to.shared.u64 t, %1; cvt.u32.u64 %0, t; }"
        : "=r"(a) : "l"(p));
    return a;
}
__device__ __forceinline__ uint32_t dsm_map(uint32_t laddr, uint32_t rank) {
    uint32_t r;
    asm("mapa.shared::cluster.u32 %0, %1, %2;" : "=r"(r) : "r"(laddr), "r"(rank));
    return r;
}
__device__ __forceinline__ void mbar_init(uint32_t a, uint32_t cnt) {
    asm volatile("mbarrier.init.shared.b64 [%0], %1;" :: "r"(a), "r"(cnt) : "memory");
}
__device__ __forceinline__ void mbar_arm(uint32_t a, uint32_t tx) {
    asm volatile("mbarrier.arrive.expect_tx.shared.b64 _, [%0], %1;"
                 :: "r"(a), "r"(tx) : "memory");
}
__device__ __forceinline__ void mbar_wait(uint32_t a, uint32_t parity) {
    asm volatile(
        "{\n\t.reg .pred P;\n\t"
        "W_%=:\n\t"
        "mbarrier.try_wait.parity.acquire.cluster.shared::cta.b64 P, [%0], %1, 0x989680;\n\t"
        "@!P bra W_%=;\n\t}"
        :: "r"(a), "r"(parity) : "memory");
}
// fire-and-forget remote store, completion counted on remote mbarrier (bytes)
__device__ __forceinline__ void st_async(uint32_t raddr, float v, uint32_t rbar) {
    asm volatile(
        "st.async.shared::cluster.mbarrier::complete_tx::bytes.b32 [%0], %1, [%2];"
        :: "r"(raddr), "r"(__float_as_uint(v)), "r"(rbar) : "memory");
}
#define CLUSTER_SYNC() do { \
    asm volatile("barrier.cluster.arrive.aligned;" ::: "memory"); \
    asm volatile("barrier.cluster.wait.aligned;"   ::: "memory"); \
} while (0)

// packed fp32x2 fma (register/broadcast-LDS operands only; NOT in GEMM)
__device__ __forceinline__ void fma2(unsigned long long& d,
                                     unsigned long long a, unsigned long long b) {
    asm("fma.rn.f32x2 %0, %1, %2, %0;" : "+l"(d) : "l"(a), "l"(b));
}
__device__ __forceinline__ unsigned long long pack2(float x, float y) {
    unsigned long long r;
    asm("mov.b64 %0, {%1, %2};" : "=l"(r) : "f"(x), "f"(y));
    return r;
}
__device__ __forceinline__ float2 unpack2(unsigned long long v) {
    float2 r;
    asm("mov.b64 {%0, %1}, %2;" : "=f"(r.x), "=f"(r.y) : "l"(v));
    return r;
}

// =======================================================================
// GEMM (R7 known-good, 58.2us): C_z = A[1024x512] @ B_z[512x512]
// 64x64 tile, BK=16, 256 threads, 4x4/thread, register prefetch.
// =======================================================================
__global__ __launch_bounds__(256) void gemm3_kernel(
    const float* __restrict__ A,
    const float* __restrict__ Ua,
    const float* __restrict__ Co,
    const float* __restrict__ Uo,
    const float* __restrict__ Ba)
{
    __shared__ float As[16][64];   // k-major
    __shared__ float Bs[16][64];

    const int m0 = blockIdx.x * 64;
    const int n0 = blockIdx.y * 64;
    const int z  = blockIdx.z;
    const float* __restrict__ Bm = (z == 0) ? Ua : ((z == 1) ? Co : Uo);
    float* Cout = (z == 0) ? g_UaH : ((z == 1) ? g_IC : g_XUo);

    const int tid  = threadIdx.x;
    const int tx   = tid & 15;
    const int ty   = tid >> 4;
    const int la_m = tid >> 2;
    const int la_k = (tid & 3) << 2;
    const int lb_k = tid >> 4;
    const int lb_n = (tid & 15) << 2;

    float acc[4][4];
    #pragma unroll
    for (int i = 0; i < 4; i++)
        #pragma unroll
        for (int j = 0; j < 4; j++) acc[i][j] = 0.f;

    float4 av = *(const float4*)&A [(m0 + la_m) * DD + la_k];
    float4 bv = *(const float4*)&Bm[lb_k * OO + n0 + lb_n];

    for (int k0 = 0; k0 < DD; k0 += 16) {
        __syncthreads();
        As[la_k + 0][la_m] = av.x;
        As[la_k + 1][la_m] = av.y;
        As[la_k + 2][la_m] = av.z;
        As[la_k + 3][la_m] = av.w;
        *(float4*)&Bs[lb_k][lb_n] = bv;
        __syncthreads();
        if (k0 + 16 < DD) {
            av = *(const float4*)&A [(m0 + la_m) * DD + (k0 + 16) + la_k];
            bv = *(const float4*)&Bm[(k0 + 16 + lb_k) * OO + n0 + lb_n];
        }
        #pragma unroll
        for (int kk = 0; kk < 16; kk++) {
            float4 a = *(const float4*)&As[kk][ty << 2];
            float4 b = *(const float4*)&Bs[kk][tx << 2];
            acc[0][0] += a.x * b.x; acc[0][1] += a.x * b.y; acc[0][2] += a.x * b.z; acc[0][3] += a.x * b.w;
            acc[1][0] += a.y * b.x; acc[1][1] += a.y * b.y; acc[1][2] += a.y * b.z; acc[1][3] += a.y * b.w;
            acc[2][0] += a.z * b.x; acc[2][1] += a.z * b.y; acc[2][2] += a.z * b.z; acc[2][3] += a.z * b.w;
            acc[3][0] += a.w * b.x; acc[3][1] += a.w * b.y; acc[3][2] += a.w * b.z; acc[3][3] += a.w * b.w;
        }
    }
    #pragma unroll
    for (int i = 0; i < 4; i++) {
        int r = m0 + (ty << 2) + i;
        #pragma unroll
        for (int j = 0; j < 4; j++) {
            int c = n0 + (tx << 2) + j;
            float v = acc[i][j];
            if (z == 0) v += Ba[c];
            Cout[(size_t)r * OO + c] = v;
        }
    }
}

// =======================================================================
// embWo[i] = sum_j emb[i][j] * Wo[j]
// =======================================================================
__global__ __launch_bounds__(256) void embwo_kernel(
    const float* __restrict__ emb, const float* __restrict__ Wo)
{
    const int row  = (blockIdx.x << 3) + (threadIdx.x >> 5);
    const int lane = threadIdx.x & 31;
    const float* rp = emb + row * OO;
    float acc = 0.f;
    #pragma unroll 4
    for (int j = lane; j < OO; j += 32) acc += rp[j] * Wo[j];
    acc = wredsum(acc);
    if (lane == 0) g_embWo[row] = acc;
}

// =======================================================================
// Persistent clustered scan (R7 protocol). ONE change: UAH_PITCH 68 -> 76.
// 76 mod 32 = 12 -> consecutive row starts cover all 8 four-bank groups ->
// P2's LDS.128 reads drop from 16 wavefronts (4-way conflict) to the 4-wf floor.
// =======================================================================
#define UAH_PITCH 76
#define SG_PITCH  68        // 64 sig + 4 scalar slots per rank
// shared memory layout (float offsets)
#define UAH_OFF   0                              // [128][76] = 9728
#define IC_OFF    (UAH_OFF + TT*UAH_PITCH)       // [128][64] = 8192
#define SG_OFF    (IC_OFF + TT*OSL)              // 2 x [8][68] = 1088
#define SPART_OFF (SG_OFF + 2*CPG*SG_PITCH)      // 2 x [8][128] = 2048
#define WAS_OFF   (SPART_OFF + 2*CPG*TT)         // [64]
#define WBUF_OFF  (WAS_OFF + OSL)                // [128]
#define RED_OFF   (WBUF_OFF + TT)                // [32]
#define PARTA_OFF (RED_OFF + 32)                 // [256]  (WaS partials)
#define PARTB_OFF (PARTA_OFF + 256)              // [256]  (P2 scores / P3 ctx)
#define BAR_OFF   (PARTB_OFF + 256)              // 4 x u64 (score0,score1,sig0,sig1)
#define SMEM_FLOATS (BAR_OFF + 8)
#define SMEM_BYTES  (SMEM_FLOATS * 4)

#define TX_SCORE (CPG*TT*4)          // 4096 bytes/phase
#define TX_SIG   (CPG*(OSL+4)*4)     // 2176 bytes/phase

__global__ __launch_bounds__(NTH, 1) __cluster_dims__(CPG, 1, 1)
void scan_kernel(const float* __restrict__ Wa,
                 const float* __restrict__ Va,
                 const float* __restrict__ Bo,
                 float* __restrict__ out)
{
    extern __shared__ float sm[];
    float* UaH_s = sm + UAH_OFF;
    float* IC_s  = sm + IC_OFF;
    float* wbuf  = sm + WBUF_OFF;
    float* WaS_s = sm + WAS_OFF;
    float* red   = sm + RED_OFF;
    float* partA = sm + PARTA_OFF;
    float* partB = sm + PARTB_OFF;

    const uint32_t sbase   = smem_u32(sm);
    const uint32_t barbase = sbase + BAR_OFF * 4;

    const int tid  = threadIdx.x;
    const int lane = tid & 31;
    const int wid  = tid >> 5;
    const int b    = blockIdx.x >> 3;     // batch
    const int crk  = blockIdx.x & 7;      // cluster rank
    const int o_base = crk * OSL;
    const int oc = tid & 63;
    const int kc = tid >> 6;              // 0..3
    const int ts = tid & 127;
    const int q  = tid >> 7;              // 0..1

    // ---------------- prologue ----------------
    for (int i = tid; i < TT * OSL; i += NTH) {
        int tt = i >> 6, o = i & 63;
        UaH_s[tt * UAH_PITCH + o] = g_UaH[(size_t)(b * TT + tt) * OO + o_base + o];
        IC_s[(tt << 6) + o]       = g_IC [(size_t)(b * TT + tt) * OO + o_base + o];
    }

    // Wa slice packed: thread (oc,kc) holds k in [kc*128, kc*128+128)
    unsigned long long wreg2[64];
    {
        const int col = o_base + oc;
        #pragma unroll
        for (int j = 0; j < 64; j++) {
            float w0 = Wa[(size_t)(kc * 128 + 2 * j)     * OO + col];
            float w1 = Wa[(size_t)(kc * 128 + 2 * j + 1) * OO + col];
            wreg2[j] = pack2(w0, w1);
        }
    }
    float va_r[32];
    #pragma unroll
    for (int j = 0; j < 32; j++) va_r[j] = Va[o_base + (q << 5) + j];

    const float ew0   = g_embWo[tid];
    const float ew1   = g_embWo[tid + 256];
    const float ew_sl = g_embWo[o_base + oc];
    const float bo_r  = (tid < OSL) ? Bo[o_base + tid] : 0.f;

    uint32_t rbase[CPG];
    #pragma unroll
    for (int r = 0; r < CPG; r++) rbase[r] = dsm_map(sbase, r);

    if (tid == 0) {
        #pragma unroll
        for (int i = 0; i < 4; i++) mbar_init(barbase + i * 8, 1);
        mbar_arm(barbase + 0,  TX_SCORE);
        mbar_arm(barbase + 8,  TX_SCORE);
        mbar_arm(barbase + 16, TX_SIG);
        mbar_arm(barbase + 24, TX_SIG);
    }

    // t=0 seed: sig(-1)=0.5, S=512, P=sum(embWo) in sg buffer 1
    float p0p = wredsum(ew0 + ew1);
    if (lane == 0) red[wid] = p0p;
    {
        float* sg1 = sm + SG_OFF + CPG * SG_PITCH;
        for (int i = tid; i < CPG * SG_PITCH; i += NTH)
            sg1[i] = ((i % SG_PITCH) < OSL) ? 0.5f : 0.f;
    }
    __syncthreads();
    if (tid == 0) {
        float P0 = 0.f;
        #pragma unroll
        for (int i = 0; i < 8; i++) P0 += red[i];
        float* sg1 = sm + SG_OFF + CPG * SG_PITCH;
        sg1[OSL + 0] = 512.f;
        sg1[OSL + 2] = P0;
    }
    __syncthreads();
    CLUSTER_SYNC();   // barriers initialized+armed everywhere before any st.async

    // ---------------- scan over T steps ----------------
    for (int t = 0; t < TT; t++) {
        const int buf = t & 1;

        float xo = 0.f;
        if (tid < OSL)
            xo = __ldg(&g_XUo[(size_t)(b * TT + ((t + TT - 1) & (TT - 1))) * OO + o_base + tid]);

        // -------- wait for sig/scalars of pred(t-1) --------
        const uint32_t sigbar_l = barbase + 16 + (buf ^ 1) * 8;
        if (t > 0) {
            mbar_wait(sigbar_l, ((t - 1) >> 1) & 1);
            if (tid == 0) mbar_arm(sigbar_l, TX_SIG);
        }
        const float* sgc = sm + SG_OFF + (buf ^ 1) * (CPG * SG_PITCH);

        // scalars -> woy (independent of WaS; overlaps with fma stream below)
        float S = 0.f, P = 0.f;
        #pragma unroll
        for (int r = 0; r < CPG; r++) {
            const float* sr = sgc + r * SG_PITCH + OSL;
            S += sr[0] + sr[1];
            P += sr[2] + sr[3];
        }
        const float woy = __fdividef(P, S);

        // -------- WaS partial (fp32x2, reg weights, broadcast sig) --------
        {
            unsigned long long acc2 = 0ull;
            #pragma unroll
            for (int rr = 0; rr < 2; rr++) {
                const ulonglong2* sp2 =
                    (const ulonglong2*)(sgc + (2 * kc + rr) * SG_PITCH);
                #pragma unroll
                for (int i = 0; i < 16; i++) {
                    ulonglong2 sv = sp2[i];
                    fma2(acc2, sv.x, wreg2[rr * 32 + 2 * i]);
                    fma2(acc2, sv.y, wreg2[rr * 32 + 2 * i + 1]);
                }
            }
            float2 f = unpack2(acc2);
            partA[tid] = f.x + f.y;
        }
        __syncthreads();                                   // s1
        if (tid < OSL)
            WaS_s[tid] = partA[tid] + partA[64 + tid] + partA[128 + tid] + partA[192 + tid];
        __syncthreads();                                   // s2

        // -------- P2: partial scores, all t, own o-half --------
        {
            const float* urow = UaH_s + ts * UAH_PITCH + (q << 5);
            const float* wp   = WaS_s + (q << 5);
            float acc = 0.f;
            #pragma unroll
            for (int j = 0; j < 8; j++) {
                float4 u = *(const float4*)&urow[j << 2];  // 4-wf floor (pitch 76)
                float4 w = *(const float4*)&wp[j << 2];    // broadcast
                acc += tanhapx(u.x + w.x) * va_r[(j << 2) + 0]
                     + tanhapx(u.y + w.y) * va_r[(j << 2) + 1]
                     + tanhapx(u.z + w.z) * va_r[(j << 2) + 2]
                     + tanhapx(u.w + w.w) * va_r[(j << 2) + 3];
            }
            partB[(q << 7) + ts] = acc;
        }
        __syncthreads();                                   // s3
        if (tid < TT) {
            float s = partB[tid] + partB[128 + tid];
            const uint32_t doff = (uint32_t)(SPART_OFF + buf * (CPG * TT) + crk * TT + tid) * 4u;
            const uint32_t boff = (uint32_t)(BAR_OFF * 4 + buf * 8);
            #pragma unroll
            for (int r = 0; r < CPG; r++)
                st_async(rbase[r] + doff, s, rbase[r] + boff);
        }

        // -------- wait for all score partials --------
        const uint32_t scorebar_l = barbase + buf * 8;
        mbar_wait(scorebar_l, (t >> 1) & 1);
        if (tid == 0) mbar_arm(scorebar_l, TX_SCORE);

        // -------- P3: softmax over T + ctx + pred + sig broadcast --------
        const float* sp = sm + SPART_OFF + buf * (CPG * TT);
        if (tid < TT) {
            float sc = 0.f;
            #pragma unroll
            for (int r = 0; r < CPG; r++) sc += sp[(r << 7) + tid];
            float esv = __expf(sc);                        // |score| small: no max-sub
            wbuf[tid] = esv;
            float spp = wredsum(esv);
            if (lane == 0) red[wid] = spp;                 // wid 0..3
        }
        __syncthreads();                                   // s4
        const float esum = (red[0] + red[1]) + (red[2] + red[3]);

        // ctx partial: thread (oc,kc) covers t' in [kc*32, kc*32+32)
        {
            float acc = 0.f;
            const int base = kc << 5;
            #pragma unroll
            for (int j = 0; j < 8; j++) {
                float4 wb = *(const float4*)&wbuf[base + (j << 2)];
                acc += wb.x * IC_s[((base + (j << 2) + 0) << 6) + oc]
                     + wb.y * IC_s[((base + (j << 2) + 1) << 6) + oc]
                     + wb.z * IC_s[((base + (j << 2) + 2) << 6) + oc]
                     + wb.w * IC_s[((base + (j << 2) + 3) << 6) + oc];
            }
            partB[tid] = acc;
        }
        __syncthreads();                                   // s5
        if (tid < OSL) {
            float ctx  = partB[tid] + partB[64 + tid] + partB[128 + tid] + partB[192 + tid];
            float pred = woy + xo + __fdividef(ctx, esum) + bo_r;
            out[(size_t)(b * TT + t) * OO + o_base + tid] = pred;

            // sigmoid + exp partials of pred(t), broadcast to all ranks
            float e  = __expf(pred);
            float sg = __fdividef(1.f, 1.f + __expf(-pred));
            float pe = wredsum(e);            // warp-local (tids 0-31 / 32-63)
            float pp = wredsum(e * ew_sl);
            if (t < TT - 1) {
                const uint32_t sgoff =
                    (uint32_t)(SG_OFF + buf * (CPG * SG_PITCH) + crk * SG_PITCH + tid) * 4u;
                const uint32_t sboff = (uint32_t)(BAR_OFF * 4 + 16 + buf * 8);
                #pragma unroll
                for (int r = 0; r < CPG; r++)
                    st_async(rbase[r] + sgoff, sg, rbase[r] + sboff);
                if (lane == 0) {
                    const int w = tid >> 5;    // 0 or 1
                    const uint32_t so =
                        (uint32_t)(SG_OFF + buf * (CPG * SG_PITCH) + crk * SG_PITCH + OSL + w) * 4u;
                    const uint32_t po = so + 8u;
                    #pragma unroll
                    for (int r = 0; r < CPG; r++) {
                        st_async(rbase[r] + so, pe, rbase[r] + sboff);
                        st_async(rbase[r] + po, pp, rbase[r] + sboff);
                    }
                }
            }
        }
    }
    CLUSTER_SYNC();   // no CTA exits while peers' in-flight stores may target it
}

// =======================================================================
// launch
// =======================================================================
extern "C" void kernel_launch(void* const* d_in, const int* in_sizes, int n_in,
                              void* d_out, int out_size)
{
    const float* inputs = (const float*)d_in[0];
    const float* Wa     = (const float*)d_in[1];
    const float* Ua     = (const float*)d_in[2];
    const float* Va     = (const float*)d_in[3];
    const float* Ba     = (const float*)d_in[4];
    const float* Wo     = (const float*)d_in[5];
    const float* Uo     = (const float*)d_in[6];
    const float* Co     = (const float*)d_in[7];
    const float* Bo     = (const float*)d_in[8];
    const float* emb    = (const float*)d_in[9];
    float* out = (float*)d_out;

    dim3 g(16, 8, 3);
    gemm3_kernel<<<g, 256>>>(inputs, Ua, Co, Uo, Ba);
    embwo_kernel<<<64, 256>>>(emb, Wo);

    cudaFuncSetAttribute(scan_kernel,
                         cudaFuncAttributeMaxDynamicSharedMemorySize, SMEM_BYTES);
    scan_kernel<<<BB * CPG, NTH, SMEM_BYTES>>>(Wa, Va, Bo, out);
}